// round 8
// baseline (speedup 1.0000x reference)
#include <cuda_runtime.h>
#include <cstdint>

// Fixed shapes from reference setup_inputs
#define B_   16
#define C_   8
#define N_   262144                     // 512*512
#define SLICES 64                       // blocks per batch
#define PIX_PER_BLOCK (N_ / SLICES)     // 4096
#define THREADS 256
#define WARPS (THREADS / 32)            // 8
#define WPX 64                          // pixels per warp-stage
#define STAGES (PIX_PER_BLOCK / WARPS / WPX)  // 8
#define DEPTH 4
#define NPART 73                        // 64 S + 8 n + 1 lse-sum
#define NBLK  (B_ * SLICES)             // 1024

// Slot: 8 channel rows of 256B; rows for ch>=4 shifted +64B (bank de-conflict).
#define SLOT_BYTES 2176
#define RING_BYTES (DEPTH * SLOT_BYTES)        // 8704
#define DYN_SMEM   (WARPS * RING_BYTES)        // 69632

__device__ float g_part[NBLK * NPART];
__device__ float g_jout[B_];
__device__ int   g_cnt_b[B_];
__device__ int   g_cnt_f;

#define FMA2(acc, a, b) \
  asm("fma.rn.f32x2 %0, %1, %2, %0;" : "+l"(acc) : "l"(a), "l"(b))

static __device__ __forceinline__ unsigned long long pack2(float lo, float hi) {
  unsigned long long r;
  asm("mov.b64 %0, {%1, %2};" : "=l"(r) : "f"(lo), "f"(hi));
  return r;
}
static __device__ __forceinline__ void unpack2(unsigned long long v,
                                               float& lo, float& hi) {
  asm("mov.b64 {%0, %1}, %2;" : "=f"(lo), "=f"(hi) : "l"(v));
}
static __device__ __forceinline__ float ex2(float x) {
  float r; asm("ex2.approx.f32 %0, %1;" : "=f"(r) : "f"(x)); return r;
}
static __device__ __forceinline__ float lg2(float x) {
  float r; asm("lg2.approx.f32 %0, %1;" : "=f"(r) : "f"(x)); return r;
}
static __device__ __forceinline__ uint32_t smem_u32(const void* p) {
  uint32_t a;
  asm("{ .reg .u64 t; cvta.to.shared.u64 t, %1; cvt.u32.u64 %0, t; }"
      : "=r"(a) : "l"(p));
  return a;
}
static __device__ __forceinline__ void cp_async16(uint32_t dst, const void* src) {
  asm volatile("cp.async.cg.shared.global [%0], [%1], 16;"
               :: "r"(dst), "l"(src) : "memory");
}
#define CP_COMMIT() asm volatile("cp.async.commit_group;" ::: "memory")
#define CP_WAIT(n)  asm volatile("cp.async.wait_group %0;" :: "n"(n) : "memory")

#define LOG2E 1.4426950408889634f
#define LN2   0.6931471805599453f

__global__ __launch_bounds__(THREADS, 3)
void jce_fused(const float* __restrict__ pred,
               const int* __restrict__ target,
               float* __restrict__ out) {
  extern __shared__ char ring[];
  __shared__ float scratch[WARPS * NPART];   // warp partials; reused in finalize
  const int bb = blockIdx.x;
  const int b  = bb >> 6;            // batch (SLICES=64)
  const int s  = bb & 63;            // slice
  const int tid  = threadIdx.x;
  const int lane = tid & 31;
  const int wid  = tid >> 5;

  const int warp_px0 = s * PIX_PER_BLOCK + wid * (STAGES * WPX);
  const float* gp = pred + (size_t)b * C_ * N_ + warp_px0;
  const int*   gt = target + (size_t)b * N_ + warp_px0;

  const uint32_t ring_base = smem_u32(ring) + wid * RING_BYTES;
  // this lane's half: even -> ch0-3 (row base 0), odd -> ch4-7 (row base 1088)
  const uint32_t half_off = (lane & 1) ? (4u * 256u + 64u) : 0u;
  const int pr = lane >> 1;          // pair index 0..15

  auto issue_stage = [&](int st) {
    const uint32_t slot = ring_base + (st & (DEPTH - 1)) * SLOT_BYTES;
    const int px0 = st * WPX;
#pragma unroll
    for (int k = 0; k < 4; ++k) {
      const int id = lane + k * 32;        // 0..127
      const int ch = id >> 4;
      const int of = id & 15;              // 16B granule within channel row
      const uint32_t row = (uint32_t)(ch * 256 + ((ch >= 4) ? 64 : 0));
      cp_async16(slot + row + (uint32_t)(of * 16),
                 gp + (size_t)ch * N_ + px0 + of * 4);
    }
    CP_COMMIT();
  };

  unsigned long long accS[16], accN[4];
#pragma unroll
  for (int i = 0; i < 16; ++i) accS[i] = 0ULL;
#pragma unroll
  for (int i = 0; i < 4; ++i) accN[i] = 0ULL;
  float lsum = 0.0f;
  const unsigned long long one2 = pack2(1.0f, 1.0f);

  issue_stage(0); issue_stage(1); issue_stage(2);

  // targets for stage 0 (both passes), prefetched while cp.async fills
  int2 tt0 = *reinterpret_cast<const int2*>(gt + (0 * 16 + pr) * 2);
  int2 tt1 = *reinterpret_cast<const int2*>(gt + (1 * 16 + pr) * 2);

#pragma unroll 2
  for (int st = 0; st < STAGES; ++st) {
    CP_WAIT(2);
    const uint32_t slot = ring_base + (st & (DEPTH - 1)) * SLOT_BYTES;

    // prefetch next stage's targets into regs (hidden under this stage's work)
    int2 nt0 = tt0, nt1 = tt1;
    if (st + 1 < STAGES) {
      const int nb = (st + 1) * WPX;
      nt0 = *reinterpret_cast<const int2*>(gt + nb + (0 * 16 + pr) * 2);
      nt1 = *reinterpret_cast<const int2*>(gt + nb + (1 * 16 + pr) * 2);
    }

#pragma unroll
    for (int h = 0; h < 2; ++h) {
      const int2 tt = h ? tt1 : tt0;
      const int p = h * 16 + pr;
      const uint32_t a0 = slot + half_off + (uint32_t)(p * 8);

      unsigned long long x[4];   // (px0, px1) per owned channel
#pragma unroll
      for (int j = 0; j < 4; ++j)
        asm volatile("ld.shared.v2.f32 {%0, %1}, [%2];"
                     : "=f"(((float2*)&x[j])->x), "=f"(((float2*)&x[j])->y)
                     : "r"(a0 + (uint32_t)(j * 256)));

      // ---- pixel 0 ----
      {
        const int t = tt.x;
        const int th = t >> 1;
        const unsigned long long hi_one =
            (t & 1) ? 0x3f80000000000000ULL : 0x000000003f800000ULL;
        unsigned long long mp[4];
#pragma unroll
        for (int j = 0; j < 4; ++j) mp[j] = (th == j) ? hi_one : 0ULL;
#pragma unroll
        for (int j = 0; j < 4; ++j) {
          const float v = ((const float2*)&x[j])->x;
          const unsigned long long vb = pack2(v, v);
#pragma unroll
          for (int kp = 0; kp < 4; ++kp) FMA2(accS[j * 4 + kp], mp[kp], vb);
        }
#pragma unroll
        for (int kp = 0; kp < 4; ++kp) FMA2(accN[kp], mp[kp], one2);
      }
      // ---- pixel 1 ----
      {
        const int t = tt.y;
        const int th = t >> 1;
        const unsigned long long hi_one =
            (t & 1) ? 0x3f80000000000000ULL : 0x000000003f800000ULL;
        unsigned long long mp[4];
#pragma unroll
        for (int j = 0; j < 4; ++j) mp[j] = (th == j) ? hi_one : 0ULL;
#pragma unroll
        for (int j = 0; j < 4; ++j) {
          const float v = ((const float2*)&x[j])->y;
          const unsigned long long vb = pack2(v, v);
#pragma unroll
          for (int kp = 0; kp < 4; ++kp) FMA2(accS[j * 4 + kp], mp[kp], vb);
        }
#pragma unroll
        for (int kp = 0; kp < 4; ++kp) FMA2(accN[kp], mp[kp], one2);
      }

      // ---- LSE: 4-channel partial exps, pair-exchange, one lg2 per lane ----
      float se0 = 0.0f, se1 = 0.0f;
#pragma unroll
      for (int j = 0; j < 4; ++j) {
        se0 += ex2(((const float2*)&x[j])->x * LOG2E);
        se1 += ex2(((const float2*)&x[j])->y * LOG2E);
      }
      const float o0 = __shfl_xor_sync(0xFFFFFFFFu, se0, 1);
      const float o1 = __shfl_xor_sync(0xFFFFFFFFu, se1, 1);
      // even lane finalizes px0, odd lane px1
      const float mysum = (lane & 1) ? (se1 + o1) : (se0 + o0);
      lsum = fmaf(LN2, lg2(mysum), lsum);
    }

    if (st + 3 < STAGES) issue_stage(st + 3);
    else CP_COMMIT();   // keep group counting aligned for CP_WAIT
    tt0 = nt0; tt1 = nt1;
  }

  // Expand owned channels into 73 scalars; unowned stay 0; warp butterfly sums.
  const int choff = (lane & 1) * 4;
  float vals[NPART];
#pragma unroll
  for (int i = 0; i < NPART; ++i) vals[i] = 0.0f;
#pragma unroll
  for (int j = 0; j < 4; ++j)
#pragma unroll
    for (int kp = 0; kp < 4; ++kp)
      unpack2(accS[j * 4 + kp], vals[(choff + j) * 8 + 2 * kp],
              vals[(choff + j) * 8 + 2 * kp + 1]);
#pragma unroll
  for (int kp = 0; kp < 4; ++kp) {
    float lo, hi;
    unpack2(accN[kp], lo, hi);
    vals[64 + 2 * kp]     = 0.5f * lo;   // n double-counted by lane pair
    vals[64 + 2 * kp + 1] = 0.5f * hi;
  }
  vals[72] = lsum;

#pragma unroll
  for (int i = 0; i < NPART; ++i) {
    float v = vals[i];
    v += __shfl_xor_sync(0xFFFFFFFFu, v, 16);
    v += __shfl_xor_sync(0xFFFFFFFFu, v, 8);
    v += __shfl_xor_sync(0xFFFFFFFFu, v, 4);
    v += __shfl_xor_sync(0xFFFFFFFFu, v, 2);
    v += __shfl_xor_sync(0xFFFFFFFFu, v, 1);
    if (lane == 0) scratch[wid * NPART + i] = v;
  }
  __syncthreads();
  if (tid < NPART) {
    float acc = 0.0f;
#pragma unroll
    for (int w2 = 0; w2 < WARPS; ++w2) acc += scratch[w2 * NPART + tid];
    g_part[bb * NPART + tid] = acc;
  }

  // ---- per-batch group-last reduction (16 run in parallel) ----
  __shared__ bool amGroupLast;
  __threadfence();
  if (tid == 0)
    amGroupLast = (atomicAdd(&g_cnt_b[b], 1) == SLICES - 1);
  __syncthreads();
  if (!amGroupLast) return;
  __threadfence();

  // reuse scratch: tot = scratch[0..72], red = scratch[73..73+256)
  float* tot = scratch;
  float* red = scratch + NPART;
  __syncthreads();
  if (tid < NPART) {
    float acc = 0.0f;
#pragma unroll 8
    for (int sl = 0; sl < SLICES; ++sl)
      acc += g_part[(b * SLICES + sl) * NPART + tid];
    tot[tid] = acc;
  }
  __syncthreads();

  const float invB  = 1.0f / (float)B_;
  const float invBN = 1.0f / ((float)B_ * (float)N_);
  float contrib = 0.0f;
  if (tid < 64) {
    const int ci = tid >> 3, ck = tid & 7;
    if (ci != ck) {
      const float diag = tot[ci * 8 + ci] / tot[64 + ci];
      const float mm   = tot[ci * 8 + ck] / tot[64 + ck];
      contrib = -(LN2 * lg2(0.5f + 0.5f * (diag - mm))) * invB;
    } else {
      contrib = -tot[ci * 8 + ci] * invBN;       // -trace part of CE
      if (tid == 0) contrib += tot[72] * invBN;  // +lse-sum part of CE
    }
  }
  red[tid] = contrib;
  __syncthreads();
#pragma unroll
  for (int off = THREADS / 2; off > 0; off >>= 1) {
    if (tid < off) red[tid] += red[tid + off];
    __syncthreads();
  }
  if (tid == 0) g_jout[b] = red[0];

  // ---- final: last of the 16 group-last blocks sums 16 floats ----
  __shared__ bool amFinal;
  __threadfence();
  if (tid == 0)
    amFinal = (atomicAdd(&g_cnt_f, 1) == B_ - 1);
  __syncthreads();
  if (!amFinal) return;
  __threadfence();

  if (tid == 0) {
    float acc = 0.0f;
#pragma unroll
    for (int i = 0; i < B_; ++i) acc += g_jout[i];
    out[0] = acc;
#pragma unroll
    for (int i = 0; i < B_; ++i) g_cnt_b[i] = 0;
    g_cnt_f = 0;
  }
}

extern "C" void kernel_launch(void* const* d_in, const int* in_sizes, int n_in,
                              void* d_out, int out_size) {
  const float* pred = (const float*)d_in[0];
  const int* target = (const int*)d_in[1];
  float* out = (float*)d_out;
  (void)in_sizes; (void)n_in; (void)out_size;

  cudaFuncSetAttribute(jce_fused, cudaFuncAttributeMaxDynamicSharedMemorySize,
                       DYN_SMEM);
  jce_fused<<<NBLK, THREADS, DYN_SMEM>>>(pred, target, out);
}

// round 9
// speedup vs baseline: 1.2098x; 1.2098x over previous
#include <cuda_runtime.h>
#include <cstdint>

// Fixed shapes from reference setup_inputs
#define B_   16
#define C_   8
#define N_   262144                     // 512*512
#define SLICES 64                       // blocks per batch
#define PIX_PER_BLOCK (N_ / SLICES)     // 4096
#define THREADS 256
#define WARPS (THREADS / 32)            // 8
#define WPX 64                          // pixels per warp-stage
#define STAGES (PIX_PER_BLOCK / WARPS / WPX)  // 8
#define DEPTH 2
#define NPART 73                        // 64 S + 8 n + 1 lse-sum
#define NBLK  (B_ * SLICES)             // 1024

#define SLOT_BYTES 2048                       // 8 ch * 64 px * 4B
#define RING_BYTES (DEPTH * SLOT_BYTES)       // 4096 per warp
#define BIN_ROWS 36                           // 32 S-pair rows + 4 n-pair rows
#define WARP_BIN (BIN_ROWS * 256)             // 9216 per warp
#define DYN_SMEM (WARPS * (WARP_BIN + RING_BYTES))  // 106496

__device__ float g_part[NBLK * NPART];
__device__ float g_jout[B_];
__device__ int   g_cnt_b[B_];
__device__ int   g_cnt_f;

#define ADD2(out, a, b) \
  asm("add.rn.f32x2 %0, %1, %2;" : "=l"(out) : "l"(a), "l"(b))

static __device__ __forceinline__ unsigned long long pack2(float lo, float hi) {
  unsigned long long r;
  asm("mov.b64 %0, {%1, %2};" : "=l"(r) : "f"(lo), "f"(hi));
  return r;
}
static __device__ __forceinline__ void unpack2(unsigned long long v,
                                               float& lo, float& hi) {
  asm("mov.b64 {%0, %1}, %2;" : "=f"(lo), "=f"(hi) : "l"(v));
}
static __device__ __forceinline__ float ex2(float x) {
  float r; asm("ex2.approx.f32 %0, %1;" : "=f"(r) : "f"(x)); return r;
}
static __device__ __forceinline__ float lg2(float x) {
  float r; asm("lg2.approx.f32 %0, %1;" : "=f"(r) : "f"(x)); return r;
}
static __device__ __forceinline__ uint32_t smem_u32(const void* p) {
  uint32_t a;
  asm("{ .reg .u64 t; cvta.to.shared.u64 t, %1; cvt.u32.u64 %0, t; }"
      : "=r"(a) : "l"(p));
  return a;
}
static __device__ __forceinline__ void cp_async16(uint32_t dst, const void* src) {
  asm volatile("cp.async.cg.shared.global [%0], [%1], 16;"
               :: "r"(dst), "l"(src) : "memory");
}
#define CP_COMMIT() asm volatile("cp.async.commit_group;" ::: "memory")
#define CP_WAIT(n)  asm volatile("cp.async.wait_group %0;" :: "n"(n) : "memory")

#define LOG2E 1.4426950408889634f
#define LN2   0.6931471805599453f

// Indexed SMEM bin update for one pixel: 4 channel-pair rows + 1 n-pair row.
static __device__ __forceinline__ void bin_px(uint32_t binl,
                                              const unsigned long long vp[4],
                                              int t) {
  const uint32_t t256 = (uint32_t)t << 8;
#pragma unroll
  for (int cip = 0; cip < 4; ++cip) {
    const uint32_t a = binl + (uint32_t)(cip * 2048) + t256;
    unsigned long long cur;
    asm volatile("ld.shared.b64 %0, [%1];" : "=l"(cur) : "r"(a));
    ADD2(cur, cur, vp[cip]);
    asm volatile("st.shared.b64 [%0], %1;" :: "r"(a), "l"(cur));
  }
  const unsigned long long nadd =
      (t & 1) ? 0x3f80000000000000ULL : 0x000000003f800000ULL;
  const uint32_t an = binl + 32u * 256u + (((uint32_t)t >> 1) << 8);
  unsigned long long cur;
  asm volatile("ld.shared.b64 %0, [%1];" : "=l"(cur) : "r"(an));
  ADD2(cur, cur, nadd);
  asm volatile("st.shared.b64 [%0], %1;" :: "r"(an), "l"(cur));
}

__global__ __launch_bounds__(THREADS, 2)
void jce_fused(const float* __restrict__ pred,
               const int* __restrict__ target,
               float* __restrict__ out) {
  extern __shared__ char dyn[];
  __shared__ float scratch[WARPS * NPART];
  const int bb = blockIdx.x;
  const int b  = bb >> 6;            // batch (SLICES=64)
  const int s  = bb & 63;            // slice
  const int tid  = threadIdx.x;
  const int lane = tid & 31;
  const int wid  = tid >> 5;

  const int warp_px0 = s * PIX_PER_BLOCK + wid * (STAGES * WPX);
  const float* gp = pred + (size_t)b * C_ * N_ + warp_px0;
  const int*   gt = target + (size_t)b * N_ + warp_px0;

  const uint32_t bin_base  = smem_u32(dyn) + wid * WARP_BIN;
  const uint32_t binl      = bin_base + (uint32_t)(lane * 8);
  const uint32_t ring_base = smem_u32(dyn) + WARPS * WARP_BIN + wid * RING_BYTES;

  auto issue_stage = [&](int st) {
    const uint32_t slot = ring_base + (st & (DEPTH - 1)) * SLOT_BYTES;
    const int px0 = st * WPX;
#pragma unroll
    for (int k = 0; k < 4; ++k) {
      const int id = lane + k * 32;        // 0..127
      const int ch = id >> 4;
      const int of = id & 15;              // 16B granule in channel row
      cp_async16(slot + (uint32_t)(ch * 256 + of * 16),
                 gp + (size_t)ch * N_ + px0 + of * 4);
    }
    CP_COMMIT();
  };

  issue_stage(0); issue_stage(1);

  // Zero this lane's private bin column (36 rows), overlapped with cp.async.
#pragma unroll
  for (int r = 0; r < BIN_ROWS; ++r)
    asm volatile("st.shared.b64 [%0], %1;"
                 :: "r"(binl + (uint32_t)(r * 256)), "l"(0ULL));

  float lsum = 0.0f;
  // Target prefetch at distance 2.
  int2 tb0 = *reinterpret_cast<const int2*>(gt + 0 * WPX + 2 * lane);
  int2 tb1 = *reinterpret_cast<const int2*>(gt + 1 * WPX + 2 * lane);

#pragma unroll 2
  for (int st = 0; st < STAGES; ++st) {
    CP_WAIT(1);
    const uint32_t slot = ring_base + (st & (DEPTH - 1)) * SLOT_BYTES;
    const int2 tt = (st & 1) ? tb1 : tb0;
    if (st + 2 < STAGES) {
      const int2 nt =
          *reinterpret_cast<const int2*>(gt + (st + 2) * WPX + 2 * lane);
      if (st & 1) tb1 = nt; else tb0 = nt;
    }

    // x[c] = (px0, px1) for channel c; px0 = 2*lane, px1 = 2*lane+1.
    unsigned long long x[8];
#pragma unroll
    for (int c = 0; c < 8; ++c)
      asm volatile("ld.shared.v2.f32 {%0, %1}, [%2];"
                   : "=f"(((float2*)&x[c])->x), "=f"(((float2*)&x[c])->y)
                   : "r"(slot + (uint32_t)(c * 256 + lane * 8)));

    // ---- pixel 0: channel-paired values, indexed bin update ----
    {
      unsigned long long vp[4];
#pragma unroll
      for (int cip = 0; cip < 4; ++cip)
        vp[cip] = pack2(((const float2*)&x[2 * cip])->x,
                        ((const float2*)&x[2 * cip + 1])->x);
      bin_px(binl, vp, tt.x);
    }
    // ---- pixel 1 ----
    {
      unsigned long long vp[4];
#pragma unroll
      for (int cip = 0; cip < 4; ++cip)
        vp[cip] = pack2(((const float2*)&x[2 * cip])->y,
                        ((const float2*)&x[2 * cip + 1])->y);
      bin_px(binl, vp, tt.y);
    }

    // ---- LSE for both pixels ----
    float se0 = 0.0f, se1 = 0.0f;
#pragma unroll
    for (int c = 0; c < 8; ++c) {
      se0 += ex2(((const float2*)&x[c])->x * LOG2E);
      se1 += ex2(((const float2*)&x[c])->y * LOG2E);
    }
    lsum = fmaf(LN2, lg2(se0), lsum);
    lsum = fmaf(LN2, lg2(se1), lsum);

    if (st + 2 < STAGES) issue_stage(st + 2);
    else CP_COMMIT();   // keep group counting aligned
  }
  CP_WAIT(0);

  // Read back this lane's bin column into 73 scalars, warp butterfly reduce.
  float vals[NPART];
#pragma unroll
  for (int cip = 0; cip < 4; ++cip)
#pragma unroll
    for (int k = 0; k < 8; ++k) {
      unsigned long long cur;
      asm volatile("ld.shared.b64 %0, [%1];"
                   : "=l"(cur) : "r"(binl + (uint32_t)((cip * 8 + k) * 256)));
      unpack2(cur, vals[(2 * cip) * 8 + k], vals[(2 * cip + 1) * 8 + k]);
    }
#pragma unroll
  for (int kp = 0; kp < 4; ++kp) {
    unsigned long long cur;
    asm volatile("ld.shared.b64 %0, [%1];"
                 : "=l"(cur) : "r"(binl + (uint32_t)((32 + kp) * 256)));
    unpack2(cur, vals[64 + 2 * kp], vals[64 + 2 * kp + 1]);
  }
  vals[72] = lsum;

#pragma unroll
  for (int i = 0; i < NPART; ++i) {
    float v = vals[i];
    v += __shfl_xor_sync(0xFFFFFFFFu, v, 16);
    v += __shfl_xor_sync(0xFFFFFFFFu, v, 8);
    v += __shfl_xor_sync(0xFFFFFFFFu, v, 4);
    v += __shfl_xor_sync(0xFFFFFFFFu, v, 2);
    v += __shfl_xor_sync(0xFFFFFFFFu, v, 1);
    if (lane == 0) scratch[wid * NPART + i] = v;
  }
  __syncthreads();
  if (tid < NPART) {
    float acc = 0.0f;
#pragma unroll
    for (int w2 = 0; w2 < WARPS; ++w2) acc += scratch[w2 * NPART + tid];
    g_part[bb * NPART + tid] = acc;
  }

  // ---- per-batch group-last reduction (16 run in parallel) ----
  __shared__ bool amGroupLast;
  __threadfence();
  if (tid == 0)
    amGroupLast = (atomicAdd(&g_cnt_b[b], 1) == SLICES - 1);
  __syncthreads();
  if (!amGroupLast) return;
  __threadfence();

  float* tot = reinterpret_cast<float*>(dyn);            // reuse dyn smem
  float* red = reinterpret_cast<float*>(dyn) + 128;
  __syncthreads();
  if (tid < NPART) {
    float acc = 0.0f;
#pragma unroll 8
    for (int sl = 0; sl < SLICES; ++sl)
      acc += g_part[(b * SLICES + sl) * NPART + tid];
    tot[tid] = acc;
  }
  __syncthreads();

  const float invB  = 1.0f / (float)B_;
  const float invBN = 1.0f / ((float)B_ * (float)N_);
  float contrib = 0.0f;
  if (tid < 64) {
    const int ci = tid >> 3, ck = tid & 7;
    if (ci != ck) {
      const float diag = tot[ci * 8 + ci] / tot[64 + ci];
      const float mm   = tot[ci * 8 + ck] / tot[64 + ck];
      contrib = -(LN2 * lg2(0.5f + 0.5f * (diag - mm))) * invB;
    } else {
      contrib = -tot[ci * 8 + ci] * invBN;       // -trace part of CE
      if (tid == 0) contrib += tot[72] * invBN;  // +lse-sum part of CE
    }
  }
  red[tid] = contrib;
  __syncthreads();
#pragma unroll
  for (int off = THREADS / 2; off > 0; off >>= 1) {
    if (tid < off) red[tid] += red[tid + off];
    __syncthreads();
  }
  if (tid == 0) g_jout[b] = red[0];

  // ---- final: last of the 16 group-last blocks sums 16 floats ----
  __shared__ bool amFinal;
  __threadfence();
  if (tid == 0)
    amFinal = (atomicAdd(&g_cnt_f, 1) == B_ - 1);
  __syncthreads();
  if (!amFinal) return;
  __threadfence();

  if (tid == 0) {
    float acc = 0.0f;
#pragma unroll
    for (int i = 0; i < B_; ++i) acc += g_jout[i];
    out[0] = acc;
#pragma unroll
    for (int i = 0; i < B_; ++i) g_cnt_b[i] = 0;
    g_cnt_f = 0;
  }
}

extern "C" void kernel_launch(void* const* d_in, const int* in_sizes, int n_in,
                              void* d_out, int out_size) {
  const float* pred = (const float*)d_in[0];
  const int* target = (const int*)d_in[1];
  float* out = (float*)d_out;
  (void)in_sizes; (void)n_in; (void)out_size;

  cudaFuncSetAttribute(jce_fused, cudaFuncAttributeMaxDynamicSharedMemorySize,
                       DYN_SMEM);
  jce_fused<<<NBLK, THREADS, DYN_SMEM>>>(pred, target, out);
}

// round 10
// speedup vs baseline: 1.6567x; 1.3693x over previous
#include <cuda_runtime.h>
#include <cstdint>

// Fixed shapes from reference setup_inputs
#define B_   16
#define C_   8
#define N_   262144                     // 512*512
#define SLICES 64                       // blocks per batch
#define PIX_PER_BLOCK (N_ / SLICES)     // 4096
#define THREADS 256
#define WARPS (THREADS / 32)            // 8
#define WPX 64                          // pixels per warp-stage
#define STAGES (PIX_PER_BLOCK / WARPS / WPX)  // 8
#define DEPTH 4
#define NPART 73                        // 64 S + 8 n + 1 lse-sum
#define NBLK  (B_ * SLICES)             // 1024

#define SLOT_BYTES 2304                 // 8 ch * 256B + 256B targets
#define RING_BYTES (DEPTH * SLOT_BYTES) // 9216 per warp
#define DYN_SMEM (WARPS * RING_BYTES)   // 73728 -> 3 CTAs/SM fit

__device__ float g_part[NBLK * NPART];
__device__ float g_jout[B_];
__device__ int   g_cnt_b[B_];
__device__ int   g_cnt_f;

static __device__ __forceinline__ float ex2(float x) {
  float r; asm("ex2.approx.f32 %0, %1;" : "=f"(r) : "f"(x)); return r;
}
static __device__ __forceinline__ float lg2(float x) {
  float r; asm("lg2.approx.f32 %0, %1;" : "=f"(r) : "f"(x)); return r;
}
static __device__ __forceinline__ uint32_t smem_u32(const void* p) {
  uint32_t a;
  asm("{ .reg .u64 t; cvta.to.shared.u64 t, %1; cvt.u32.u64 %0, t; }"
      : "=r"(a) : "l"(p));
  return a;
}
static __device__ __forceinline__ void cp_async16(uint32_t dst, const void* src) {
  asm volatile("cp.async.cg.shared.global [%0], [%1], 16;"
               :: "r"(dst), "l"(src) : "memory");
}
#define CP_COMMIT() asm volatile("cp.async.commit_group;" ::: "memory")
#define CP_WAIT(n)  asm volatile("cp.async.wait_group %0;" :: "n"(n) : "memory")

// pack two f32 -> f16x2; first source lands in HIGH half, second in LOW half.
static __device__ __forceinline__ uint32_t f16pack(float hi, float lo) {
  uint32_t r;
  asm("cvt.rn.f16x2.f32 %0, %1, %2;" : "=r"(r) : "f"(hi), "f"(lo));
  return r;
}

#define LOG2E 1.4426950408889634f
#define LN2   0.6931471805599453f

__global__ __launch_bounds__(THREADS, 3)
void jce_fused(const float* __restrict__ pred,
               const int* __restrict__ target,
               float* __restrict__ out) {
  extern __shared__ char dyn[];
  __shared__ bool amGroupLast, amFinal;
  const int bb = blockIdx.x;
  const int b  = bb >> 6;            // batch (SLICES=64)
  const int s  = bb & 63;            // slice
  const int tid  = threadIdx.x;
  const int lane = tid & 31;
  const int wid  = tid >> 5;
  const int ci   = lane >> 2;        // MMA group id = channel row
  const int tig  = lane & 3;         // thread-in-group

  const int warp_px0 = s * PIX_PER_BLOCK + wid * (STAGES * WPX);
  const float* gp = pred + (size_t)b * C_ * N_ + warp_px0;
  const int*   gt = target + (size_t)b * N_ + warp_px0;
  const uint32_t ring_base = smem_u32(dyn) + wid * RING_BYTES;

  auto issue_stage = [&](int st) {
    const uint32_t slot = ring_base + (st & (DEPTH - 1)) * SLOT_BYTES;
    const int px0 = st * WPX;
#pragma unroll
    for (int k = 0; k < 4; ++k) {
      const int id = lane + k * 32;        // 0..127
      const int ch = id >> 4;
      const int of = id & 15;              // 16B granule in channel row
      cp_async16(slot + (uint32_t)(ch * 256 + of * 16),
                 gp + (size_t)ch * N_ + px0 + of * 4);
    }
    if (lane < 16)
      cp_async16(slot + (uint32_t)(C_ * 256 + lane * 16), gt + px0 + lane * 4);
    CP_COMMIT();
  };

  // D fragments: dX[0..1] = S[ci][tig*2 .. +1]; dX[2..3] = n[tig*2 .. +1]
  float dA0 = 0, dA1 = 0, dA2 = 0, dA3 = 0;   // even K-chunks
  float dB0 = 0, dB1 = 0, dB2 = 0, dB3 = 0;   // odd K-chunks
  float lsum = 0.0f;
  const uint32_t ones2 = 0x3c003c00u;  // fp16 (1.0, 1.0)

  issue_stage(0); issue_stage(1); issue_stage(2);

#pragma unroll 2
  for (int st = 0; st < STAGES; ++st) {
    CP_WAIT(2);
    const uint32_t slot = ring_base + (st & (DEPTH - 1)) * SLOT_BYTES;

    // ---- LSE on this lane's own 2 pixels (px 2*lane, 2*lane+1) ----
    float2 x[8];
#pragma unroll
    for (int c = 0; c < 8; ++c)
      asm volatile("ld.shared.v2.f32 {%0, %1}, [%2];"
                   : "=f"(x[c].x), "=f"(x[c].y)
                   : "r"(slot + (uint32_t)(c * 256 + lane * 8)));
    float se0 = 0.0f, se1 = 0.0f;
#pragma unroll
    for (int c = 0; c < 8; ++c) {
      se0 += ex2(x[c].x * LOG2E);
      se1 += ex2(x[c].y * LOG2E);
    }
    lsum = fmaf(LN2, lg2(se0), lsum);
    lsum = fmaf(LN2, lg2(se1), lsum);

    // ---- 4 MMA K-chunks of 16 pixels each ----
#pragma unroll
    for (int q = 0; q < 4; ++q) {
      const uint32_t off = (uint32_t)(q * 64 + tig * 8);  // (q*16+tig*2)*4 bytes

      // A frag: pred[ci][k0,k1] and [k8,k9] as f16x2 (low half = k0/k8)
      float2 alo, ahi;
      asm volatile("ld.shared.v2.f32 {%0, %1}, [%2];"
                   : "=f"(alo.x), "=f"(alo.y)
                   : "r"(slot + (uint32_t)(ci * 256) + off));
      asm volatile("ld.shared.v2.f32 {%0, %1}, [%2];"
                   : "=f"(ahi.x), "=f"(ahi.y)
                   : "r"(slot + (uint32_t)(ci * 256) + off + 32u));
      const uint32_t ra0 = f16pack(alo.y, alo.x);
      const uint32_t ra2 = f16pack(ahi.y, ahi.x);

      // B frag: onehot[k][ci] from targets (broadcast LDS, 4 distinct addrs)
      int2 tA, tB;
      asm volatile("ld.shared.v2.s32 {%0, %1}, [%2];"
                   : "=r"(tA.x), "=r"(tA.y)
                   : "r"(slot + 2048u + off));
      asm volatile("ld.shared.v2.s32 {%0, %1}, [%2];"
                   : "=r"(tB.x), "=r"(tB.y)
                   : "r"(slot + 2048u + off + 32u));
      const uint32_t rb0 = (tA.x == ci ? 0x3c00u : 0u) |
                           (tA.y == ci ? 0x3c000000u : 0u);
      const uint32_t rb1 = (tB.x == ci ? 0x3c00u : 0u) |
                           (tB.y == ci ? 0x3c000000u : 0u);

      if (q & 1)
        asm volatile(
            "mma.sync.aligned.m16n8k16.row.col.f32.f16.f16.f32 "
            "{%0,%1,%2,%3}, {%4,%5,%6,%7}, {%8,%9}, {%0,%1,%2,%3};"
            : "+f"(dB0), "+f"(dB1), "+f"(dB2), "+f"(dB3)
            : "r"(ra0), "r"(ones2), "r"(ra2), "r"(ones2), "r"(rb0), "r"(rb1));
      else
        asm volatile(
            "mma.sync.aligned.m16n8k16.row.col.f32.f16.f16.f32 "
            "{%0,%1,%2,%3}, {%4,%5,%6,%7}, {%8,%9}, {%0,%1,%2,%3};"
            : "+f"(dA0), "+f"(dA1), "+f"(dA2), "+f"(dA3)
            : "r"(ra0), "r"(ones2), "r"(ra2), "r"(ones2), "r"(rb0), "r"(rb1));
    }

    if (st + 3 < STAGES) issue_stage(st + 3);
    else CP_COMMIT();   // keep group counting aligned for CP_WAIT
  }
  CP_WAIT(0);

  const float d0 = dA0 + dB0, d1 = dA1 + dB1;
  const float d2 = dA2 + dB2, d3 = dA3 + dB3;

  // warp-reduce lsum
  lsum += __shfl_xor_sync(0xFFFFFFFFu, lsum, 16);
  lsum += __shfl_xor_sync(0xFFFFFFFFu, lsum, 8);
  lsum += __shfl_xor_sync(0xFFFFFFFFu, lsum, 4);
  lsum += __shfl_xor_sync(0xFFFFFFFFu, lsum, 2);
  lsum += __shfl_xor_sync(0xFFFFFFFFu, lsum, 1);

  // Per-warp 73 partials into this warp's (now idle) ring area.
  float* wsc = reinterpret_cast<float*>(dyn + (size_t)wid * RING_BYTES);
  *reinterpret_cast<float2*>(wsc + ci * 8 + tig * 2) = make_float2(d0, d1);
  if (ci == 0)
    *reinterpret_cast<float2*>(wsc + 64 + tig * 2) = make_float2(d2, d3);
  if (lane == 0) wsc[72] = lsum;
  __syncthreads();

  if (tid < NPART) {
    float acc = 0.0f;
#pragma unroll
    for (int w2 = 0; w2 < WARPS; ++w2)
      acc += reinterpret_cast<const float*>(dyn + (size_t)w2 * RING_BYTES)[tid];
    g_part[bb * NPART + tid] = acc;
  }

  // ---- per-batch group-last reduction (16 run in parallel) ----
  __threadfence();
  if (tid == 0)
    amGroupLast = (atomicAdd(&g_cnt_b[b], 1) == SLICES - 1);
  __syncthreads();
  if (!amGroupLast) return;
  __threadfence();

  float* tot = reinterpret_cast<float*>(dyn);        // 73 floats
  float* red = reinterpret_cast<float*>(dyn) + 128;  // 256 floats
  if (tid < NPART) {
    float acc = 0.0f;
#pragma unroll 8
    for (int sl = 0; sl < SLICES; ++sl)
      acc += g_part[(b * SLICES + sl) * NPART + tid];
    tot[tid] = acc;
  }
  __syncthreads();

  const float invB  = 1.0f / (float)B_;
  const float invBN = 1.0f / ((float)B_ * (float)N_);
  float contrib = 0.0f;
  if (tid < 64) {
    const int cii = tid >> 3, ck = tid & 7;
    if (cii != ck) {
      const float diag = tot[cii * 8 + cii] / tot[64 + cii];
      const float mm   = tot[cii * 8 + ck] / tot[64 + ck];
      contrib = -(LN2 * lg2(0.5f + 0.5f * (diag - mm))) * invB;
    } else {
      contrib = -tot[cii * 8 + cii] * invBN;      // -trace part of CE
      if (tid == 0) contrib += tot[72] * invBN;   // +lse-sum part of CE
    }
  }
  red[tid] = contrib;
  __syncthreads();
#pragma unroll
  for (int off = THREADS / 2; off > 0; off >>= 1) {
    if (tid < off) red[tid] += red[tid + off];
    __syncthreads();
  }
  if (tid == 0) g_jout[b] = red[0];

  // ---- final: last of the 16 group-last blocks sums 16 floats ----
  __threadfence();
  if (tid == 0)
    amFinal = (atomicAdd(&g_cnt_f, 1) == B_ - 1);
  __syncthreads();
  if (!amFinal) return;
  __threadfence();

  if (tid == 0) {
    float acc = 0.0f;
#pragma unroll
    for (int i = 0; i < B_; ++i) acc += g_jout[i];
    out[0] = acc;
#pragma unroll
    for (int i = 0; i < B_; ++i) g_cnt_b[i] = 0;
    g_cnt_f = 0;
  }
}

extern "C" void kernel_launch(void* const* d_in, const int* in_sizes, int n_in,
                              void* d_out, int out_size) {
  const float* pred = (const float*)d_in[0];
  const int* target = (const int*)d_in[1];
  float* out = (float*)d_out;
  (void)in_sizes; (void)n_in; (void)out_size;

  cudaFuncSetAttribute(jce_fused, cudaFuncAttributeMaxDynamicSharedMemorySize,
                       DYN_SMEM);
  jce_fused<<<NBLK, THREADS, DYN_SMEM>>>(pred, target, out);
}

// round 11
// speedup vs baseline: 1.7565x; 1.0602x over previous
#include <cuda_runtime.h>
#include <cstdint>

// Fixed shapes from reference setup_inputs
#define B_   16
#define C_   8
#define N_   262144                     // 512*512
#define SLICES 64                       // blocks per batch
#define PIX_PER_BLOCK (N_ / SLICES)     // 4096
#define THREADS 256
#define WARPS (THREADS / 32)            // 8
#define WPX 64                          // pixels per warp-stage
#define STAGES (PIX_PER_BLOCK / WARPS / WPX)  // 8
#define DEPTH 4
#define NPART 73                        // 64 S + 8 n + 1 lse-sum
#define NBLK  (B_ * SLICES)             // 1024

#define SLOT_BYTES 2304                 // 8 ch * 256B + 256B targets
#define RING_BYTES (DEPTH * SLOT_BYTES) // 9216 per warp
#define DYN_SMEM (WARPS * RING_BYTES)   // 73728 -> 3 CTAs/SM fit

// Bank-deconflict swizzle: 16B granule g of channel ch stored at g ^ (2*ch).
#define SWZ(ch, g) ((uint32_t)(((g) ^ (2 * (ch))) & 15))

__device__ float g_part[NBLK * NPART];
__device__ float g_jout[B_];
__device__ int   g_cnt_b[B_];
__device__ int   g_cnt_f;

static __device__ __forceinline__ float ex2(float x) {
  float r; asm("ex2.approx.f32 %0, %1;" : "=f"(r) : "f"(x)); return r;
}
static __device__ __forceinline__ float lg2(float x) {
  float r; asm("lg2.approx.f32 %0, %1;" : "=f"(r) : "f"(x)); return r;
}
static __device__ __forceinline__ uint32_t smem_u32(const void* p) {
  uint32_t a;
  asm("{ .reg .u64 t; cvta.to.shared.u64 t, %1; cvt.u32.u64 %0, t; }"
      : "=r"(a) : "l"(p));
  return a;
}
static __device__ __forceinline__ void cp_async16(uint32_t dst, const void* src) {
  asm volatile("cp.async.cg.shared.global [%0], [%1], 16;"
               :: "r"(dst), "l"(src) : "memory");
}
#define CP_COMMIT() asm volatile("cp.async.commit_group;" ::: "memory")
#define CP_WAIT(n)  asm volatile("cp.async.wait_group %0;" :: "n"(n) : "memory")

// pack two f32 -> f16x2; first source lands in HIGH half, second in LOW half.
static __device__ __forceinline__ uint32_t f16pack(float hi, float lo) {
  uint32_t r;
  asm("cvt.rn.f16x2.f32 %0, %1, %2;" : "=r"(r) : "f"(hi), "f"(lo));
  return r;
}

#define LOG2E 1.4426950408889634f
#define LN2   0.6931471805599453f

__global__ __launch_bounds__(THREADS, 3)
void jce_fused(const float* __restrict__ pred,
               const int* __restrict__ target,
               float* __restrict__ out) {
  extern __shared__ char dyn[];
  __shared__ bool amGroupLast, amFinal;
  const int bb = blockIdx.x;
  const int b  = bb >> 6;            // batch (SLICES=64)
  const int s  = bb & 63;            // slice
  const int tid  = threadIdx.x;
  const int lane = tid & 31;
  const int wid  = tid >> 5;
  const int ci   = lane >> 2;        // MMA group id = channel row
  const int tig  = lane & 3;         // thread-in-group

  const int warp_px0 = s * PIX_PER_BLOCK + wid * (STAGES * WPX);
  const float* gp = pred + (size_t)b * C_ * N_ + warp_px0;
  const int*   gt = target + (size_t)b * N_ + warp_px0;
  const uint32_t ring_base = smem_u32(dyn) + wid * RING_BYTES;

  auto issue_stage = [&](int st) {
    const uint32_t slot = ring_base + (st & (DEPTH - 1)) * SLOT_BYTES;
    const int px0 = st * WPX;
#pragma unroll
    for (int k = 0; k < 4; ++k) {
      const int id = lane + k * 32;        // 0..127
      const int ch = id >> 4;
      const int of = id & 15;              // 16B granule in channel row
      cp_async16(slot + (uint32_t)(ch * 256) + SWZ(ch, of) * 16u,
                 gp + (size_t)ch * N_ + px0 + of * 4);
    }
    if (lane < 16)
      cp_async16(slot + (uint32_t)(C_ * 256 + lane * 16), gt + px0 + lane * 4);
    CP_COMMIT();
  };

  // D fragments: dX[0..1] = S[ci][tig*2 .. +1]; dX[2..3] = n[tig*2 .. +1]
  float dA0 = 0, dA1 = 0, dA2 = 0, dA3 = 0;   // even K-chunks
  float dB0 = 0, dB1 = 0, dB2 = 0, dB3 = 0;   // odd K-chunks
  float lsum2 = 0.0f;                  // LSE accumulated in log2 units
  const uint32_t ones2 = 0x3c003c00u;  // fp16 (1.0, 1.0)

  issue_stage(0); issue_stage(1); issue_stage(2);

#pragma unroll 2
  for (int st = 0; st < STAGES; ++st) {
    CP_WAIT(2);
    const uint32_t slot = ring_base + (st & (DEPTH - 1)) * SLOT_BYTES;

    // ---- LSE on this lane's own 2 pixels (px 2*lane, 2*lane+1) ----
    float2 x[8];
#pragma unroll
    for (int c = 0; c < 8; ++c)
      asm volatile("ld.shared.v2.f32 {%0, %1}, [%2];"
                   : "=f"(x[c].x), "=f"(x[c].y)
                   : "r"(slot + (uint32_t)(c * 256) +
                         SWZ(c, lane >> 1) * 16u + (uint32_t)((lane & 1) * 8)));
    float se0 = 0.0f, se1 = 0.0f;
#pragma unroll
    for (int c = 0; c < 8; ++c) {
      se0 += ex2(x[c].x * LOG2E);
      se1 += ex2(x[c].y * LOG2E);
    }
    lsum2 += lg2(se0) + lg2(se1);

    // ---- 4 MMA K-chunks of 16 pixels each ----
#pragma unroll
    for (int q = 0; q < 4; ++q) {
      const uint32_t wb = (uint32_t)((tig & 1) * 8);   // byte-in-granule
      const int glo = q * 4 + (tig >> 1);              // granule of k0,k1
      const uint32_t alo_a = slot + (uint32_t)(ci * 256) + SWZ(ci, glo) * 16u + wb;
      const uint32_t ahi_a = slot + (uint32_t)(ci * 256) + SWZ(ci, glo + 2) * 16u + wb;

      // A frag: pred[ci][k0,k1] and [k8,k9] as f16x2 (low half = k0/k8)
      float2 alo, ahi;
      asm volatile("ld.shared.v2.f32 {%0, %1}, [%2];"
                   : "=f"(alo.x), "=f"(alo.y) : "r"(alo_a));
      asm volatile("ld.shared.v2.f32 {%0, %1}, [%2];"
                   : "=f"(ahi.x), "=f"(ahi.y) : "r"(ahi_a));
      const uint32_t ra0 = f16pack(alo.y, alo.x);
      const uint32_t ra2 = f16pack(ahi.y, ahi.x);

      // B frag: onehot[k][ci] from targets (broadcast LDS, unswizzled row)
      const uint32_t off = (uint32_t)(q * 64 + tig * 8);
      int2 tA, tB;
      asm volatile("ld.shared.v2.s32 {%0, %1}, [%2];"
                   : "=r"(tA.x), "=r"(tA.y) : "r"(slot + 2048u + off));
      asm volatile("ld.shared.v2.s32 {%0, %1}, [%2];"
                   : "=r"(tB.x), "=r"(tB.y) : "r"(slot + 2048u + off + 32u));
      const uint32_t rb0 = (tA.x == ci ? 0x3c00u : 0u) |
                           (tA.y == ci ? 0x3c000000u : 0u);
      const uint32_t rb1 = (tB.x == ci ? 0x3c00u : 0u) |
                           (tB.y == ci ? 0x3c000000u : 0u);

      if (q & 1)
        asm volatile(
            "mma.sync.aligned.m16n8k16.row.col.f32.f16.f16.f32 "
            "{%0,%1,%2,%3}, {%4,%5,%6,%7}, {%8,%9}, {%0,%1,%2,%3};"
            : "+f"(dB0), "+f"(dB1), "+f"(dB2), "+f"(dB3)
            : "r"(ra0), "r"(ones2), "r"(ra2), "r"(ones2), "r"(rb0), "r"(rb1));
      else
        asm volatile(
            "mma.sync.aligned.m16n8k16.row.col.f32.f16.f16.f32 "
            "{%0,%1,%2,%3}, {%4,%5,%6,%7}, {%8,%9}, {%0,%1,%2,%3};"
            : "+f"(dA0), "+f"(dA1), "+f"(dA2), "+f"(dA3)
            : "r"(ra0), "r"(ones2), "r"(ra2), "r"(ones2), "r"(rb0), "r"(rb1));
    }

    if (st + 3 < STAGES) issue_stage(st + 3);
    else CP_COMMIT();   // keep group counting aligned for CP_WAIT
  }
  CP_WAIT(0);

  const float d0 = dA0 + dB0, d1 = dA1 + dB1;
  const float d2 = dA2 + dB2, d3 = dA3 + dB3;
  float lsum = lsum2 * LN2;

  // warp-reduce lsum
  lsum += __shfl_xor_sync(0xFFFFFFFFu, lsum, 16);
  lsum += __shfl_xor_sync(0xFFFFFFFFu, lsum, 8);
  lsum += __shfl_xor_sync(0xFFFFFFFFu, lsum, 4);
  lsum += __shfl_xor_sync(0xFFFFFFFFu, lsum, 2);
  lsum += __shfl_xor_sync(0xFFFFFFFFu, lsum, 1);

  // Per-warp 73 partials into this warp's (now idle) ring area.
  float* wsc = reinterpret_cast<float*>(dyn + (size_t)wid * RING_BYTES);
  *reinterpret_cast<float2*>(wsc + ci * 8 + tig * 2) = make_float2(d0, d1);
  if (ci == 0)
    *reinterpret_cast<float2*>(wsc + 64 + tig * 2) = make_float2(d2, d3);
  if (lane == 0) wsc[72] = lsum;
  __syncthreads();

  if (tid < NPART) {
    float acc = 0.0f;
#pragma unroll
    for (int w2 = 0; w2 < WARPS; ++w2)
      acc += reinterpret_cast<const float*>(dyn + (size_t)w2 * RING_BYTES)[tid];
    g_part[bb * NPART + tid] = acc;
  }

  // ---- per-batch group-last reduction (16 run in parallel) ----
  __threadfence();
  if (tid == 0)
    amGroupLast = (atomicAdd(&g_cnt_b[b], 1) == SLICES - 1);
  __syncthreads();
  if (!amGroupLast) return;
  __threadfence();

  float* tot = reinterpret_cast<float*>(dyn);        // 73 floats
  float* red = reinterpret_cast<float*>(dyn) + 128;  // 256 floats
  if (tid < NPART) {
    float acc = 0.0f;
#pragma unroll 8
    for (int sl = 0; sl < SLICES; ++sl)
      acc += g_part[(b * SLICES + sl) * NPART + tid];
    tot[tid] = acc;
  }
  __syncthreads();

  const float invB  = 1.0f / (float)B_;
  const float invBN = 1.0f / ((float)B_ * (float)N_);
  float contrib = 0.0f;
  if (tid < 64) {
    const int cii = tid >> 3, ck = tid & 7;
    if (cii != ck) {
      const float diag = tot[cii * 8 + cii] / tot[64 + cii];
      const float mm   = tot[cii * 8 + ck] / tot[64 + ck];
      contrib = -(LN2 * lg2(0.5f + 0.5f * (diag - mm))) * invB;
    } else {
      contrib = -tot[cii * 8 + cii] * invBN;      // -trace part of CE
      if (tid == 0) contrib += tot[72] * invBN;   // +lse-sum part of CE
    }
  }
  red[tid] = contrib;
  __syncthreads();
#pragma unroll
  for (int off = THREADS / 2; off > 0; off >>= 1) {
    if (tid < off) red[tid] += red[tid + off];
    __syncthreads();
  }
  if (tid == 0) g_jout[b] = red[0];

  // ---- final: last of the 16 group-last blocks sums 16 floats ----
  __threadfence();
  if (tid == 0)
    amFinal = (atomicAdd(&g_cnt_f, 1) == B_ - 1);
  __syncthreads();
  if (!amFinal) return;
  __threadfence();

  if (tid == 0) {
    float acc = 0.0f;
#pragma unroll
    for (int i = 0; i < B_; ++i) acc += g_jout[i];
    out[0] = acc;
#pragma unroll
    for (int i = 0; i < B_; ++i) g_cnt_b[i] = 0;
    g_cnt_f = 0;
  }
}

extern "C" void kernel_launch(void* const* d_in, const int* in_sizes, int n_in,
                              void* d_out, int out_size) {
  const float* pred = (const float*)d_in[0];
  const int* target = (const int*)d_in[1];
  float* out = (float*)d_out;
  (void)in_sizes; (void)n_in; (void)out_size;

  cudaFuncSetAttribute(jce_fused, cudaFuncAttributeMaxDynamicSharedMemorySize,
                       DYN_SMEM);
  jce_fused<<<NBLK, THREADS, DYN_SMEM>>>(pred, target, out);
}